// round 6
// baseline (speedup 1.0000x reference)
#include <cuda_runtime.h>
#include <math.h>

#define BATCH 64
#define TT    256
#define EMBD  256
#define HH    1024
#define H3    3072

// Scratch: xw[dir][s*BATCH+b][3H]  (backward already time-reversed).  ~402 MB bss.
__device__ float g_xw[2][TT * BATCH][H3];
__device__ unsigned int g_arrive[2];

// ---------------------------------------------------------------------------
// Kernel A: xw = gather(emb, x) @ W + b_input      (both directions)
// Tiled fp32 GEMM, M=16384 (n = s*B+b), N=3072, K=256. grid (256, 48, 2).
// Also resets the scan grid-barrier counters (runs before the scan kernel).
// ---------------------------------------------------------------------------
__global__ void __launch_bounds__(128) xw_gemm_kernel(
    const int* __restrict__ x,
    const float* __restrict__ emb,
    const float* __restrict__ Wf,
    const float* __restrict__ bf,
    const float* __restrict__ Wb,
    const float* __restrict__ bb)
{
    if (blockIdx.x == 0 && blockIdx.y == 0 && blockIdx.z == 0 && threadIdx.x == 0) {
        g_arrive[0] = 0u;
        g_arrive[1] = 0u;
    }

    __shared__ float As[32][68];   // As[k][m]
    __shared__ float Bs[32][68];   // Bs[k][n]

    const int dir = blockIdx.z;
    const float* __restrict__ W    = dir ? Wb : Wf;
    const float* __restrict__ bias = dir ? bb : bf;   // row 0 = input bias

    const int m0  = blockIdx.x * 64;
    const int n0  = blockIdx.y * 64;
    const int tid = threadIdx.x;

    const int r0 = (tid >> 4) * 8;    // 8 output rows
    const int c0 = (tid & 15) * 4;    // 4 output cols

    float acc[8][4] = {};

    for (int k0 = 0; k0 < EMBD; k0 += 32) {
        // ---- A tile fill (embedding gather), 512 float4s ----
        #pragma unroll
        for (int i = 0; i < 4; i++) {
            int q4 = i * 128 + tid;
            int m  = q4 >> 3;        // 0..63
            int k4 = q4 & 7;         // 0..7
            int n  = m0 + m;
            int s  = n >> 6;         // n / BATCH
            int b  = n & 63;         // n % BATCH
            int t  = dir ? (TT - 1 - s) : s;
            int tok = x[b * TT + t];
            float4 v = *(const float4*)(emb + (size_t)tok * EMBD + k0 + k4 * 4);
            As[k4 * 4 + 0][m] = v.x;
            As[k4 * 4 + 1][m] = v.y;
            As[k4 * 4 + 2][m] = v.z;
            As[k4 * 4 + 3][m] = v.w;
        }
        // ---- B tile fill, 512 float4s ----
        #pragma unroll
        for (int i = 0; i < 4; i++) {
            int q4 = i * 128 + tid;
            int k  = q4 >> 4;        // 0..31
            int nf = q4 & 15;        // 0..15
            float4 v = *(const float4*)(W + (size_t)(k0 + k) * H3 + n0 + nf * 4);
            *(float4*)&Bs[k][nf * 4] = v;
        }
        __syncthreads();

        #pragma unroll
        for (int k = 0; k < 32; k++) {
            float4 a0 = *(float4*)&As[k][r0];
            float4 a1 = *(float4*)&As[k][r0 + 4];
            float4 bv = *(float4*)&Bs[k][c0];
            float a[8] = {a0.x, a0.y, a0.z, a0.w, a1.x, a1.y, a1.z, a1.w};
            float bb4[4] = {bv.x, bv.y, bv.z, bv.w};
            #pragma unroll
            for (int ii = 0; ii < 8; ii++)
                #pragma unroll
                for (int jj = 0; jj < 4; jj++)
                    acc[ii][jj] += a[ii] * bb4[jj];
        }
        __syncthreads();
    }

    // ---- store + input bias ----
    const int j = n0 + c0;
    float4 bi = *(const float4*)(bias + j);
    #pragma unroll
    for (int ii = 0; ii < 8; ii++) {
        int n = m0 + r0 + ii;
        float4 o;
        o.x = acc[ii][0] + bi.x;
        o.y = acc[ii][1] + bi.y;
        o.z = acc[ii][2] + bi.z;
        o.w = acc[ii][3] + bi.w;
        *(float4*)&g_xw[dir][n][j] = o;
    }
}

// ---------------------------------------------------------------------------
// Kernel B: persistent bidirectional GRU scan.
// 128 blocks (64 per direction), 128 threads. Block owns 16 h-cols (48 gate
// cols). h state is read/written directly in the output concat buffer.
// Per-direction grid barrier via cumulative atomic counter.
// ---------------------------------------------------------------------------
__global__ void __launch_bounds__(128, 1) gru_scan_kernel(
    const float* __restrict__ hidden,
    const float* __restrict__ Uf,
    const float* __restrict__ bf,
    const float* __restrict__ Ub,
    const float* __restrict__ bb,
    float* __restrict__ out)
{
    __shared__ float As[32][68];   // h_prev[k][b]
    __shared__ float Bs[32][52];   // U[k][gate*16 + colFrac]

    const int blk = blockIdx.x;
    const int dir = blk >> 6;                 // 64 blocks per direction
    const int cb  = (blk & 63) * 16;          // h-column base

    const float* __restrict__ U    = dir ? Ub : Uf;
    const float* __restrict__ brow = (dir ? bb : bf) + H3;  // recurrent bias (row 1)

    const int tid = threadIdx.x;
    const int r0  = (tid >> 4) * 8;           // 8 batch rows
    const int cl  = tid & 15;
    const int c   = cb + cl;                  // my h-column

    const float bz_b = brow[c];
    const float br_b = brow[c + HH];
    const float bh_b = brow[c + 2 * HH];

    const float* __restrict__ xwbase = &g_xw[dir][0][0];
    const unsigned nb = 64;

    for (int s = 0; s < TT; s++) {
        float accz[8] = {}, accr[8] = {}, acch[8] = {};

        for (int k0 = 0; k0 < HH; k0 += 32) {
            // ---- fill As with h_prev (transposed), 512 float4s ----
            #pragma unroll
            for (int i = 0; i < 4; i++) {
                int q4 = i * 128 + tid;
                int b  = q4 >> 3;     // 0..63
                int k4 = q4 & 7;      // 0..7
                const float* hp;
                if (s == 0)           hp = hidden + (size_t)b * HH;
                else if (dir == 0)    hp = out + ((size_t)b * TT + (s - 1)) * 2048;
                else                  hp = out + ((size_t)b * TT + (TT - s)) * 2048 + HH;
                float4 v = __ldcg((const float4*)(hp + k0 + k4 * 4));
                As[k4 * 4 + 0][b] = v.x;
                As[k4 * 4 + 1][b] = v.y;
                As[k4 * 4 + 2][b] = v.z;
                As[k4 * 4 + 3][b] = v.w;
            }
            // ---- fill Bs with U slice: 32 k-rows x 48 cols = 384 float4s ----
            #pragma unroll
            for (int i = 0; i < 3; i++) {
                int q4   = i * 128 + tid;
                int k    = q4 / 12;
                int slot = q4 - k * 12;
                int g    = slot >> 2;
                int f    = slot & 3;
                float4 v = *(const float4*)(U + (size_t)(k0 + k) * H3 + g * HH + cb + f * 4);
                *(float4*)&Bs[k][g * 16 + f * 4] = v;
            }
            __syncthreads();

            #pragma unroll
            for (int k = 0; k < 32; k++) {
                float4 a0 = *(float4*)&As[k][r0];
                float4 a1 = *(float4*)&As[k][r0 + 4];
                float bz = Bs[k][cl];
                float br = Bs[k][16 + cl];
                float bh = Bs[k][32 + cl];
                float a[8] = {a0.x, a0.y, a0.z, a0.w, a1.x, a1.y, a1.z, a1.w};
                #pragma unroll
                for (int ii = 0; ii < 8; ii++) {
                    accz[ii] += a[ii] * bz;
                    accr[ii] += a[ii] * br;
                    acch[ii] += a[ii] * bh;
                }
            }
            __syncthreads();
        }

        // ---- gates + state update ----
        const size_t xrow = (size_t)s * BATCH;
        const int time = dir ? (TT - 1 - s) : s;
        #pragma unroll
        for (int ii = 0; ii < 8; ii++) {
            int b = r0 + ii;
            const float* xw = xwbase + (xrow + b) * H3;
            float xz = xw[c];
            float xr = xw[c + HH];
            float xh = xw[c + 2 * HH];
            const float* hp;
            if (s == 0)        hp = hidden + (size_t)b * HH;
            else if (dir == 0) hp = out + ((size_t)b * TT + (s - 1)) * 2048;
            else               hp = out + ((size_t)b * TT + (TT - s)) * 2048 + HH;
            float hprev = __ldcg(hp + c);

            float z    = 1.f / (1.f + expf(-(xz + accz[ii] + bz_b)));
            float r    = 1.f / (1.f + expf(-(xr + accr[ii] + br_b)));
            float cand = tanhf(xh + r * (acch[ii] + bh_b));
            float hn   = z * hprev + (1.f - z) * cand;

            out[((size_t)b * TT + time) * 2048 + dir * HH + c] = hn;
            if (s == TT - 1) {
                // hf / hb tail outputs
                out[(size_t)BATCH * TT * 2048 + (size_t)dir * BATCH * HH + (size_t)b * HH + c] = hn;
            }
        }

        // ---- per-direction grid barrier ----
        if (s < TT - 1) {
            __syncthreads();
            if (tid == 0) {
                __threadfence();
                atomicAdd(&g_arrive[dir], 1u);
                unsigned target = nb * (unsigned)(s + 1);
                while (*(volatile unsigned*)&g_arrive[dir] < target) {
                    __nanosleep(32);
                }
            }
            __syncthreads();
        }
    }
}

// ---------------------------------------------------------------------------
extern "C" void kernel_launch(void* const* d_in, const int* in_sizes, int n_in,
                              void* d_out, int out_size)
{
    const int*   x      = (const int*)  d_in[0];
    const float* hidden = (const float*)d_in[1];
    const float* emb    = (const float*)d_in[2];
    const float* Wf     = (const float*)d_in[3];
    const float* Uf     = (const float*)d_in[4];
    const float* bf     = (const float*)d_in[5];
    const float* Wb     = (const float*)d_in[6];
    const float* Ub     = (const float*)d_in[7];
    const float* bb     = (const float*)d_in[8];
    float* out = (float*)d_out;

    dim3 ga(256, 48, 2);                       // M-tiles x N-tiles x dir
    xw_gemm_kernel<<<ga, 128>>>(x, emb, Wf, bf, Wb, bb);
    gru_scan_kernel<<<128, 128>>>(hidden, Uf, bf, Ub, bb, out);
}